// round 14
// baseline (speedup 1.0000x reference)
#include <cuda_runtime.h>
#include <math.h>

// Problem constants (fixed by the reference setup_inputs).
#define B_ 8
#define L_ 1024
#define E_ 1024
#define H_ 16
#define D_ 64

// Scratch (allocation-free rule: __device__ globals).
// Layouts: g_Qp/g_Kp/g_Vp : [B*H][L][D]   g_Oa : [B][L][E]
__device__ float g_Qp[(size_t)B_ * H_ * L_ * D_];
__device__ float g_Kp[(size_t)B_ * H_ * L_ * D_];
__device__ float g_Vp[(size_t)B_ * H_ * L_ * D_];
__device__ float g_Oa[(size_t)B_ * L_ * E_];

// ---------------------------------------------------------------------------
// Kernel 1: per-head projection.
// out[b,h,l,e] = sum_d X[b,l,h*D+d] * W[h,e,d]
// Block: 64 l-rows x 64 e-cols for one (b,h). 256 threads, 4x4 micro-tile.
// ---------------------------------------------------------------------------
__global__ void __launch_bounds__(256) proj_kernel(const float* __restrict__ X,
                                                   const float* __restrict__ W,
                                                   int which) {
    __shared__ float Xt[64 * 64];  // [d][l]
    __shared__ float Wt[64 * 64];  // [d][e]

    const int tid = threadIdx.x;
    const int bh  = blockIdx.y;
    const int b   = bh >> 4;
    const int h   = bh & 15;
    const int l0  = blockIdx.x * 64;
    const int tx  = tid & 15;
    const int ty  = tid >> 4;
    const int d4  = ty * 4;

    const float* Xb = X + ((size_t)b * L_ + l0) * E_ + h * D_;
    const float* Wh = W + (size_t)h * D_ * D_;

    // Load X tile (rows=l) and W (rows=e) transposed into smem.
    // row index lives in the low lanes -> conflict-free-ish transposed stores.
#pragma unroll
    for (int r = 0; r < 4; ++r) {
        int row = tx + r * 16;
        float4 x = *(const float4*)(Xb + (size_t)row * E_ + d4);
        Xt[(d4 + 0) * 64 + row] = x.x;
        Xt[(d4 + 1) * 64 + row] = x.y;
        Xt[(d4 + 2) * 64 + row] = x.z;
        Xt[(d4 + 3) * 64 + row] = x.w;
        float4 w = *(const float4*)(Wh + (size_t)row * D_ + d4);
        Wt[(d4 + 0) * 64 + row] = w.x;
        Wt[(d4 + 1) * 64 + row] = w.y;
        Wt[(d4 + 2) * 64 + row] = w.z;
        Wt[(d4 + 3) * 64 + row] = w.w;
    }
    __syncthreads();

    float acc[4][4];
#pragma unroll
    for (int r = 0; r < 4; ++r)
#pragma unroll
        for (int c = 0; c < 4; ++c) acc[r][c] = 0.0f;

#pragma unroll 8
    for (int d = 0; d < 64; ++d) {
        float4 xf = *(const float4*)(Xt + d * 64 + ty * 4);  // broadcast
        float4 wf = *(const float4*)(Wt + d * 64 + tx * 4);  // conflict-free
        float xr[4] = {xf.x, xf.y, xf.z, xf.w};
        float wc[4] = {wf.x, wf.y, wf.z, wf.w};
#pragma unroll
        for (int r = 0; r < 4; ++r)
#pragma unroll
            for (int c = 0; c < 4; ++c)
                acc[r][c] = fmaf(xr[r], wc[c], acc[r][c]);
    }

    float* O = (which == 0) ? g_Vp : (which == 1) ? g_Kp : g_Qp;
    O += ((size_t)bh * L_ + l0) * D_;
#pragma unroll
    for (int r = 0; r < 4; ++r) {
        *(float4*)(O + (size_t)(ty * 4 + r) * D_ + tx * 4) =
            make_float4(acc[r][0], acc[r][1], acc[r][2], acc[r][3]);
    }
}

// ---------------------------------------------------------------------------
// Kernel 2: flash-style attention for one (b,h) and 64 query rows.
// S = (Q K^T) masked, scaled by 1/8; online softmax; O = P V.
// 256 threads. Smem: Qt + (K reused as P) + V = 48 KB exactly.
// Thread (ty,tx): S rows i=ty*4+r, S cols j=tx*4+c; O rows i, O cols d=tx*4+c.
// ---------------------------------------------------------------------------
__global__ void __launch_bounds__(256) attn_kernel(const int* __restrict__ mask) {
    __shared__ float Qt[64 * 64];   // [d][i]
    __shared__ float KPt[64 * 64];  // K phase: [d][j];  P phase: [i][j]
    __shared__ float Vs[64 * 64];   // [j][d]

    const int tid = threadIdx.x;
    const int bh  = blockIdx.y;
    const int b   = bh >> 4;
    const int h   = bh & 15;
    const int i0  = blockIdx.x * 64;
    const int tx  = tid & 15;
    const int ty  = tid >> 4;
    const int d4  = ty * 4;

    const float* Qb = g_Qp + (size_t)bh * L_ * D_;
    const float* Kb = g_Kp + (size_t)bh * L_ * D_;
    const float* Vb = g_Vp + (size_t)bh * L_ * D_;
    const int*   mb = mask + (size_t)b * L_ * L_;

    // Load Q tile transposed once.
#pragma unroll
    for (int r = 0; r < 4; ++r) {
        int row = tx + r * 16;
        float4 q = *(const float4*)(Qb + (size_t)(i0 + row) * D_ + d4);
        Qt[(d4 + 0) * 64 + row] = q.x;
        Qt[(d4 + 1) * 64 + row] = q.y;
        Qt[(d4 + 2) * 64 + row] = q.z;
        Qt[(d4 + 3) * 64 + row] = q.w;
    }

    float m_i[4], l_i[4], acc[4][4];
#pragma unroll
    for (int r = 0; r < 4; ++r) {
        m_i[r] = -1.0e30f;
        l_i[r] = 0.0f;
#pragma unroll
        for (int c = 0; c < 4; ++c) acc[r][c] = 0.0f;
    }

    for (int j0 = 0; j0 < L_; j0 += 64) {
        __syncthreads();  // previous P/V consumers done (also covers Qt on iter 0)
        // Load K tile transposed + V tile natural.
#pragma unroll
        for (int r = 0; r < 4; ++r) {
            int row = tx + r * 16;
            float4 k = *(const float4*)(Kb + (size_t)(j0 + row) * D_ + d4);
            KPt[(d4 + 0) * 64 + row] = k.x;
            KPt[(d4 + 1) * 64 + row] = k.y;
            KPt[(d4 + 2) * 64 + row] = k.z;
            KPt[(d4 + 3) * 64 + row] = k.w;
            int rowv = ty + r * 16;
            float4 v = *(const float4*)(Vb + (size_t)(j0 + rowv) * D_ + tx * 4);
            *(float4*)(Vs + rowv * 64 + tx * 4) = v;
        }
        __syncthreads();

        // S = Q K^T  (unscaled)
        float s[4][4];
#pragma unroll
        for (int r = 0; r < 4; ++r)
#pragma unroll
            for (int c = 0; c < 4; ++c) s[r][c] = 0.0f;

#pragma unroll 8
        for (int d = 0; d < 64; ++d) {
            float4 qf = *(const float4*)(Qt + d * 64 + ty * 4);
            float4 kf = *(const float4*)(KPt + d * 64 + tx * 4);
            float qr[4] = {qf.x, qf.y, qf.z, qf.w};
            float kc[4] = {kf.x, kf.y, kf.z, kf.w};
#pragma unroll
            for (int r = 0; r < 4; ++r)
#pragma unroll
                for (int c = 0; c < 4; ++c)
                    s[r][c] = fmaf(qr[r], kc[c], s[r][c]);
        }

        // Mask (-1e20 pre-scale, exactly like reference), scale, online softmax.
        float p[4][4];
#pragma unroll
        for (int r = 0; r < 4; ++r) {
            int4 mk = *(const int4*)(mb + (size_t)(i0 + ty * 4 + r) * L_ + j0 + tx * 4);
            s[r][0] = 0.125f * ((mk.x == 0) ? -1.0e20f : s[r][0]);
            s[r][1] = 0.125f * ((mk.y == 0) ? -1.0e20f : s[r][1]);
            s[r][2] = 0.125f * ((mk.z == 0) ? -1.0e20f : s[r][2]);
            s[r][3] = 0.125f * ((mk.w == 0) ? -1.0e20f : s[r][3]);

            float mloc = fmaxf(fmaxf(s[r][0], s[r][1]), fmaxf(s[r][2], s[r][3]));
#pragma unroll
            for (int o = 8; o > 0; o >>= 1)
                mloc = fmaxf(mloc, __shfl_xor_sync(0xffffffffu, mloc, o));
            float mnew = fmaxf(m_i[r], mloc);
            float a = __expf(m_i[r] - mnew);
            float rsum = 0.0f;
#pragma unroll
            for (int c = 0; c < 4; ++c) {
                p[r][c] = __expf(s[r][c] - mnew);
                rsum += p[r][c];
            }
#pragma unroll
            for (int o = 8; o > 0; o >>= 1)
                rsum += __shfl_xor_sync(0xffffffffu, rsum, o);
            l_i[r] = l_i[r] * a + rsum;
            m_i[r] = mnew;
#pragma unroll
            for (int c = 0; c < 4; ++c) acc[r][c] *= a;
        }

        __syncthreads();  // everyone done reading K from KPt
        // Write P row-major (float4 stores -> conflict-free).
#pragma unroll
        for (int r = 0; r < 4; ++r) {
            *(float4*)(KPt + (ty * 4 + r) * 64 + tx * 4) =
                make_float4(p[r][0], p[r][1], p[r][2], p[r][3]);
        }
        __syncthreads();

        // O[i][d] += sum_j P[i][j] * V[j][d]
#pragma unroll 8
        for (int j = 0; j < 64; ++j) {
            float4 vf = *(const float4*)(Vs + j * 64 + tx * 4);
            float p0 = KPt[(ty * 4 + 0) * 64 + j];  // broadcast reads
            float p1 = KPt[(ty * 4 + 1) * 64 + j];
            float p2 = KPt[(ty * 4 + 2) * 64 + j];
            float p3 = KPt[(ty * 4 + 3) * 64 + j];
            acc[0][0] = fmaf(p0, vf.x, acc[0][0]);
            acc[0][1] = fmaf(p0, vf.y, acc[0][1]);
            acc[0][2] = fmaf(p0, vf.z, acc[0][2]);
            acc[0][3] = fmaf(p0, vf.w, acc[0][3]);
            acc[1][0] = fmaf(p1, vf.x, acc[1][0]);
            acc[1][1] = fmaf(p1, vf.y, acc[1][1]);
            acc[1][2] = fmaf(p1, vf.z, acc[1][2]);
            acc[1][3] = fmaf(p1, vf.w, acc[1][3]);
            acc[2][0] = fmaf(p2, vf.x, acc[2][0]);
            acc[2][1] = fmaf(p2, vf.y, acc[2][1]);
            acc[2][2] = fmaf(p2, vf.z, acc[2][2]);
            acc[2][3] = fmaf(p2, vf.w, acc[2][3]);
            acc[3][0] = fmaf(p3, vf.x, acc[3][0]);
            acc[3][1] = fmaf(p3, vf.y, acc[3][1]);
            acc[3][2] = fmaf(p3, vf.z, acc[3][2]);
            acc[3][3] = fmaf(p3, vf.w, acc[3][3]);
        }
    }

    // Epilogue: normalize and write concat-head layout [B][L][E].
    float* Ob = g_Oa + ((size_t)b * L_ + i0) * E_ + h * D_;
#pragma unroll
    for (int r = 0; r < 4; ++r) {
        float inv = 1.0f / l_i[r];
        *(float4*)(Ob + (size_t)(ty * 4 + r) * E_ + tx * 4) =
            make_float4(acc[r][0] * inv, acc[r][1] * inv,
                        acc[r][2] * inv, acc[r][3] * inv);
    }
}

// ---------------------------------------------------------------------------
// Kernel 3: output projection  Y = Oa @ Wo^T + bo.
// [8192 x 1024] x [1024 x 1024]^T. 128x128 tiles, BK=16, 8x8 micro-tile.
// ---------------------------------------------------------------------------
__global__ void __launch_bounds__(256) oproj_kernel(const float* __restrict__ Wo,
                                                    const float* __restrict__ bo,
                                                    float* __restrict__ Y) {
    __shared__ float As[16 * 132];  // [k][m], padded
    __shared__ float Bs[16 * 132];  // [k][n], padded

    const int tid = threadIdx.x;
    const int n0  = blockIdx.x * 128;
    const int m0  = blockIdx.y * 128;
    const int tx8 = tid & 15;
    const int ty8 = tid >> 4;
    const int kq  = (tid >> 6) * 4;  // 0,4,8,12
    const int mm  = tid & 63;

    float acc[8][8];
#pragma unroll
    for (int r = 0; r < 8; ++r)
#pragma unroll
        for (int c = 0; c < 8; ++c) acc[r][c] = 0.0f;

    const float* Ab = g_Oa + (size_t)m0 * E_;
    const float* Bb = Wo + (size_t)n0 * E_;

    for (int k0 = 0; k0 < E_; k0 += 16) {
        __syncthreads();
#pragma unroll
        for (int pss = 0; pss < 2; ++pss) {
            int row = mm + pss * 64;
            float4 a = *(const float4*)(Ab + (size_t)row * E_ + k0 + kq);
            As[(kq + 0) * 132 + row] = a.x;
            As[(kq + 1) * 132 + row] = a.y;
            As[(kq + 2) * 132 + row] = a.z;
            As[(kq + 3) * 132 + row] = a.w;
            float4 w = *(const float4*)(Bb + (size_t)row * E_ + k0 + kq);
            Bs[(kq + 0) * 132 + row] = w.x;
            Bs[(kq + 1) * 132 + row] = w.y;
            Bs[(kq + 2) * 132 + row] = w.z;
            Bs[(kq + 3) * 132 + row] = w.w;
        }
        __syncthreads();

#pragma unroll
        for (int k = 0; k < 16; ++k) {
            float4 t0 = *(const float4*)(As + k * 132 + ty8 * 8);
            float4 t1 = *(const float4*)(As + k * 132 + ty8 * 8 + 4);
            float4 u0 = *(const float4*)(Bs + k * 132 + tx8 * 8);
            float4 u1 = *(const float4*)(Bs + k * 132 + tx8 * 8 + 4);
            float av[8] = {t0.x, t0.y, t0.z, t0.w, t1.x, t1.y, t1.z, t1.w};
            float bv[8] = {u0.x, u0.y, u0.z, u0.w, u1.x, u1.y, u1.z, u1.w};
#pragma unroll
            for (int r = 0; r < 8; ++r)
#pragma unroll
                for (int c = 0; c < 8; ++c)
                    acc[r][c] = fmaf(av[r], bv[c], acc[r][c]);
        }
    }

#pragma unroll
    for (int r = 0; r < 8; ++r) {
        int m = m0 + ty8 * 8 + r;
#pragma unroll
        for (int cg = 0; cg < 2; ++cg) {
            int n = n0 + tx8 * 8 + cg * 4;
            float4 bb = *(const float4*)(bo + n);
            *(float4*)(Y + (size_t)m * E_ + n) =
                make_float4(acc[r][cg * 4 + 0] + bb.x, acc[r][cg * 4 + 1] + bb.y,
                            acc[r][cg * 4 + 2] + bb.z, acc[r][cg * 4 + 3] + bb.w);
        }
    }
}

// ---------------------------------------------------------------------------
extern "C" void kernel_launch(void* const* d_in, const int* in_sizes, int n_in,
                              void* d_out, int out_size) {
    const float* values = (const float*)d_in[0];
    const float* keys   = (const float*)d_in[1];
    const float* query  = (const float*)d_in[2];
    const int*   mask   = (const int*)d_in[3];

    // Input 4 is the scalar "size" if it was materialized; be defensive.
    int base = 4;
    if (n_in >= 10 && in_sizes[4] == 1) base = 5;
    const float* Wv = (const float*)d_in[base + 0];
    const float* Wk = (const float*)d_in[base + 1];
    const float* Wq = (const float*)d_in[base + 2];
    const float* Wo = (const float*)d_in[base + 3];
    const float* bo = (const float*)d_in[base + 4];
    float* out = (float*)d_out;

    dim3 pgrid(L_ / 64, B_ * H_);
    proj_kernel<<<pgrid, 256>>>(values, Wv, 0);
    proj_kernel<<<pgrid, 256>>>(keys,   Wk, 1);
    proj_kernel<<<pgrid, 256>>>(query,  Wq, 2);

    dim3 agrid(L_ / 64, B_ * H_);
    attn_kernel<<<agrid, 256>>>(mask);

    dim3 ogrid(E_ / 128, (B_ * L_) / 128);
    oproj_kernel<<<ogrid, 256>>>(Wo, bo, out);
}

// round 15
// speedup vs baseline: 1.0112x; 1.0112x over previous
#include <cuda_runtime.h>
#include <math.h>

// Problem constants (fixed by the reference setup_inputs).
#define B_ 8
#define L_ 1024
#define E_ 1024
#define H_ 16
#define D_ 64

typedef unsigned long long u64t;

// ---- packed fp32x2 helpers (Blackwell FFMA2 path) -------------------------
__device__ __forceinline__ u64t splat2(float x) {
    u64t r;
    unsigned u = __float_as_uint(x);
    asm("mov.b64 %0, {%1, %1};" : "=l"(r) : "r"(u));
    return r;
}
__device__ __forceinline__ u64t fma2(u64t a, u64t b, u64t c) {
    u64t d;
    asm("fma.rn.f32x2 %0, %1, %2, %3;" : "=l"(d) : "l"(a), "l"(b), "l"(c));
    return d;
}
__device__ __forceinline__ u64t mul2(u64t a, u64t b) {
    u64t d;
    asm("mul.rn.f32x2 %0, %1, %2;" : "=l"(d) : "l"(a), "l"(b));
    return d;
}
__device__ __forceinline__ float2 unpack2(u64t a) {
    unsigned lo, hi;
    asm("mov.b64 {%0, %1}, %2;" : "=r"(lo), "=r"(hi) : "l"(a));
    return make_float2(__uint_as_float(lo), __uint_as_float(hi));
}

// Scratch (allocation-free rule: __device__ globals).
// Layouts: g_Qp/g_Kp/g_Vp : [B*H][L][D]   g_Oa : [B][L][E]
__device__ float g_Qp[(size_t)B_ * H_ * L_ * D_];
__device__ float g_Kp[(size_t)B_ * H_ * L_ * D_];
__device__ float g_Vp[(size_t)B_ * H_ * L_ * D_];
__device__ float g_Oa[(size_t)B_ * L_ * E_];

// ---------------------------------------------------------------------------
// Kernel 1: per-head QKV projection, fused (blockIdx.z selects V/K/Q).
// out[b,h,l,e] = sum_d X[b,l,h*D+d] * W[h,e,d]
// Block: 64 l-rows x 64 e-cols for one (b,h). 256 threads, 4x4 micro-tile.
// ---------------------------------------------------------------------------
__global__ void __launch_bounds__(256) proj_kernel(
    const float* __restrict__ Xv, const float* __restrict__ Xk,
    const float* __restrict__ Xq, const float* __restrict__ Wv,
    const float* __restrict__ Wk, const float* __restrict__ Wq) {
    __shared__ float Xt[64 * 64];  // [d][l]
    __shared__ float Wt[64 * 64];  // [d][e]

    const int tid   = threadIdx.x;
    const int which = blockIdx.z;
    const int bh    = blockIdx.y;
    const int b     = bh >> 4;
    const int h     = bh & 15;
    const int l0    = blockIdx.x * 64;
    const int tx    = tid & 15;
    const int ty    = tid >> 4;
    const int d4    = ty * 4;

    const float* X = (which == 0) ? Xv : (which == 1) ? Xk : Xq;
    const float* W = (which == 0) ? Wv : (which == 1) ? Wk : Wq;
    const float* Xb = X + ((size_t)b * L_ + l0) * E_ + h * D_;
    const float* Wh = W + (size_t)h * D_ * D_;

#pragma unroll
    for (int r = 0; r < 4; ++r) {
        int row = tx + r * 16;
        float4 x = *(const float4*)(Xb + (size_t)row * E_ + d4);
        Xt[(d4 + 0) * 64 + row] = x.x;
        Xt[(d4 + 1) * 64 + row] = x.y;
        Xt[(d4 + 2) * 64 + row] = x.z;
        Xt[(d4 + 3) * 64 + row] = x.w;
        float4 w = *(const float4*)(Wh + (size_t)row * D_ + d4);
        Wt[(d4 + 0) * 64 + row] = w.x;
        Wt[(d4 + 1) * 64 + row] = w.y;
        Wt[(d4 + 2) * 64 + row] = w.z;
        Wt[(d4 + 3) * 64 + row] = w.w;
    }
    __syncthreads();

    u64t acc2[4][2];
#pragma unroll
    for (int r = 0; r < 4; ++r) { acc2[r][0] = 0ull; acc2[r][1] = 0ull; }

#pragma unroll 8
    for (int d = 0; d < 64; ++d) {
        float4 xf = *(const float4*)(Xt + d * 64 + ty * 4);          // broadcast
        ulonglong2 wf = *(const ulonglong2*)(Wt + d * 64 + tx * 4);  // packed pairs
        u64t x0 = splat2(xf.x), x1 = splat2(xf.y), x2 = splat2(xf.z), x3 = splat2(xf.w);
        acc2[0][0] = fma2(x0, wf.x, acc2[0][0]);
        acc2[0][1] = fma2(x0, wf.y, acc2[0][1]);
        acc2[1][0] = fma2(x1, wf.x, acc2[1][0]);
        acc2[1][1] = fma2(x1, wf.y, acc2[1][1]);
        acc2[2][0] = fma2(x2, wf.x, acc2[2][0]);
        acc2[2][1] = fma2(x2, wf.y, acc2[2][1]);
        acc2[3][0] = fma2(x3, wf.x, acc2[3][0]);
        acc2[3][1] = fma2(x3, wf.y, acc2[3][1]);
    }

    float* O = (which == 0) ? g_Vp : (which == 1) ? g_Kp : g_Qp;
    O += ((size_t)bh * L_ + l0) * D_;
#pragma unroll
    for (int r = 0; r < 4; ++r) {
        float2 a = unpack2(acc2[r][0]);
        float2 c = unpack2(acc2[r][1]);
        *(float4*)(O + (size_t)(ty * 4 + r) * D_ + tx * 4) =
            make_float4(a.x, a.y, c.x, c.y);
    }
}

// ---------------------------------------------------------------------------
// Kernel 2: flash-style attention for one (b,h) and 64 query rows.
// S = (Q K^T) masked, scaled by 1/8; online softmax; O = P V.
// 256 threads, 48 KB smem. f32x2-packed FMAs in both GEMMs.
// ---------------------------------------------------------------------------
__global__ void __launch_bounds__(256) attn_kernel(const int* __restrict__ mask) {
    __shared__ float Qt[64 * 64];   // [d][i]
    __shared__ float KPt[64 * 64];  // K phase: [d][j];  P phase: [i][j]
    __shared__ float Vs[64 * 64];   // [j][d]

    const int tid = threadIdx.x;
    const int bh  = blockIdx.y;
    const int b   = bh >> 4;
    const int i0  = blockIdx.x * 64;
    const int tx  = tid & 15;
    const int ty  = tid >> 4;
    const int d4  = ty * 4;

    const float* Qb = g_Qp + (size_t)bh * L_ * D_;
    const float* Kb = g_Kp + (size_t)bh * L_ * D_;
    const float* Vb = g_Vp + (size_t)bh * L_ * D_;
    const int*   mb = mask + (size_t)b * L_ * L_;

    // Load Q tile transposed once.
#pragma unroll
    for (int r = 0; r < 4; ++r) {
        int row = tx + r * 16;
        float4 q = *(const float4*)(Qb + (size_t)(i0 + row) * D_ + d4);
        Qt[(d4 + 0) * 64 + row] = q.x;
        Qt[(d4 + 1) * 64 + row] = q.y;
        Qt[(d4 + 2) * 64 + row] = q.z;
        Qt[(d4 + 3) * 64 + row] = q.w;
    }

    float m_i[4], l_i[4];
    u64t acc2[4][2];
#pragma unroll
    for (int r = 0; r < 4; ++r) {
        m_i[r] = -1.0e30f;
        l_i[r] = 0.0f;
        acc2[r][0] = 0ull;
        acc2[r][1] = 0ull;
    }

    for (int j0 = 0; j0 < L_; j0 += 64) {
        __syncthreads();  // previous P/V consumers done (covers Qt on iter 0)
#pragma unroll
        for (int r = 0; r < 4; ++r) {
            int row = tx + r * 16;
            float4 k = *(const float4*)(Kb + (size_t)(j0 + row) * D_ + d4);
            KPt[(d4 + 0) * 64 + row] = k.x;
            KPt[(d4 + 1) * 64 + row] = k.y;
            KPt[(d4 + 2) * 64 + row] = k.z;
            KPt[(d4 + 3) * 64 + row] = k.w;
            int rowv = ty + r * 16;
            float4 v = *(const float4*)(Vb + (size_t)(j0 + rowv) * D_ + tx * 4);
            *(float4*)(Vs + rowv * 64 + tx * 4) = v;
        }
        __syncthreads();

        // S = Q K^T (packed pairs along j)
        u64t s2[4][2];
#pragma unroll
        for (int r = 0; r < 4; ++r) { s2[r][0] = 0ull; s2[r][1] = 0ull; }

#pragma unroll 8
        for (int d = 0; d < 64; ++d) {
            float4 qf = *(const float4*)(Qt + d * 64 + ty * 4);           // broadcast
            ulonglong2 kf = *(const ulonglong2*)(KPt + d * 64 + tx * 4);  // packed
            u64t q0 = splat2(qf.x), q1 = splat2(qf.y), q2 = splat2(qf.z), q3 = splat2(qf.w);
            s2[0][0] = fma2(q0, kf.x, s2[0][0]);
            s2[0][1] = fma2(q0, kf.y, s2[0][1]);
            s2[1][0] = fma2(q1, kf.x, s2[1][0]);
            s2[1][1] = fma2(q1, kf.y, s2[1][1]);
            s2[2][0] = fma2(q2, kf.x, s2[2][0]);
            s2[2][1] = fma2(q2, kf.y, s2[2][1]);
            s2[3][0] = fma2(q3, kf.x, s2[3][0]);
            s2[3][1] = fma2(q3, kf.y, s2[3][1]);
        }

        // Mask (-1e20 pre-scale, exactly like reference), scale, online softmax.
        float p[4][4];
#pragma unroll
        for (int r = 0; r < 4; ++r) {
            float s[4];
            float2 a0 = unpack2(s2[r][0]);
            float2 a1 = unpack2(s2[r][1]);
            s[0] = a0.x; s[1] = a0.y; s[2] = a1.x; s[3] = a1.y;

            int4 mk = *(const int4*)(mb + (size_t)(i0 + ty * 4 + r) * L_ + j0 + tx * 4);
            s[0] = 0.125f * ((mk.x == 0) ? -1.0e20f : s[0]);
            s[1] = 0.125f * ((mk.y == 0) ? -1.0e20f : s[1]);
            s[2] = 0.125f * ((mk.z == 0) ? -1.0e20f : s[2]);
            s[3] = 0.125f * ((mk.w == 0) ? -1.0e20f : s[3]);

            float mloc = fmaxf(fmaxf(s[0], s[1]), fmaxf(s[2], s[3]));
#pragma unroll
            for (int o = 8; o > 0; o >>= 1)
                mloc = fmaxf(mloc, __shfl_xor_sync(0xffffffffu, mloc, o));
            float mnew = fmaxf(m_i[r], mloc);
            float a = __expf(m_i[r] - mnew);
            float rsum = 0.0f;
#pragma unroll
            for (int c = 0; c < 4; ++c) {
                p[r][c] = __expf(s[c] - mnew);
                rsum += p[r][c];
            }
#pragma unroll
            for (int o = 8; o > 0; o >>= 1)
                rsum += __shfl_xor_sync(0xffffffffu, rsum, o);
            l_i[r] = l_i[r] * a + rsum;
            m_i[r] = mnew;
            u64t a2 = splat2(a);
            acc2[r][0] = mul2(acc2[r][0], a2);
            acc2[r][1] = mul2(acc2[r][1], a2);
        }

        __syncthreads();  // everyone done reading K from KPt
#pragma unroll
        for (int r = 0; r < 4; ++r) {
            *(float4*)(KPt + (ty * 4 + r) * 64 + tx * 4) =
                make_float4(p[r][0], p[r][1], p[r][2], p[r][3]);
        }
        __syncthreads();

        // O[i][d] += sum_j P[i][j] * V[j][d]   (packed pairs along d)
#pragma unroll 8
        for (int j = 0; j < 64; ++j) {
            ulonglong2 vf = *(const ulonglong2*)(Vs + j * 64 + tx * 4);
            u64t p0 = splat2(KPt[(ty * 4 + 0) * 64 + j]);  // broadcast reads
            u64t p1 = splat2(KPt[(ty * 4 + 1) * 64 + j]);
            u64t p2 = splat2(KPt[(ty * 4 + 2) * 64 + j]);
            u64t p3 = splat2(KPt[(ty * 4 + 3) * 64 + j]);
            acc2[0][0] = fma2(p0, vf.x, acc2[0][0]);
            acc2[0][1] = fma2(p0, vf.y, acc2[0][1]);
            acc2[1][0] = fma2(p1, vf.x, acc2[1][0]);
            acc2[1][1] = fma2(p1, vf.y, acc2[1][1]);
            acc2[2][0] = fma2(p2, vf.x, acc2[2][0]);
            acc2[2][1] = fma2(p2, vf.y, acc2[2][1]);
            acc2[3][0] = fma2(p3, vf.x, acc2[3][0]);
            acc2[3][1] = fma2(p3, vf.y, acc2[3][1]);
        }
    }

    // Epilogue: normalize, write concat-head layout [B][L][E].
    const int h = bh & 15;
    float* Ob = g_Oa + ((size_t)b * L_ + i0) * E_ + h * D_;
#pragma unroll
    for (int r = 0; r < 4; ++r) {
        float inv = 1.0f / l_i[r];
        float2 a = unpack2(acc2[r][0]);
        float2 c = unpack2(acc2[r][1]);
        *(float4*)(Ob + (size_t)(ty * 4 + r) * E_ + tx * 4) =
            make_float4(a.x * inv, a.y * inv, c.x * inv, c.y * inv);
    }
}

// ---------------------------------------------------------------------------
// Kernel 3: output projection  Y = Oa @ Wo^T + bo.
// [8192 x 1024] x [1024 x 1024]^T. 128x128 tiles, BK=16, 8x8 micro-tile, f32x2.
// ---------------------------------------------------------------------------
__global__ void __launch_bounds__(256) oproj_kernel(const float* __restrict__ Wo,
                                                    const float* __restrict__ bo,
                                                    float* __restrict__ Y) {
    __shared__ float As[16 * 132];  // [k][m], padded (132*4 = 528 B, 16B-multiple)
    __shared__ float Bs[16 * 132];  // [k][n], padded

    const int tid = threadIdx.x;
    const int n0  = blockIdx.x * 128;
    const int m0  = blockIdx.y * 128;
    const int tx8 = tid & 15;
    const int ty8 = tid >> 4;
    const int kq  = (tid >> 6) * 4;  // 0,4,8,12
    const int mm  = tid & 63;

    u64t acc2[8][4];
#pragma unroll
    for (int r = 0; r < 8; ++r)
#pragma unroll
        for (int c = 0; c < 4; ++c) acc2[r][c] = 0ull;

    const float* Ab = g_Oa + (size_t)m0 * E_;
    const float* Bb = Wo + (size_t)n0 * E_;

    for (int k0 = 0; k0 < E_; k0 += 16) {
        __syncthreads();
#pragma unroll
        for (int pss = 0; pss < 2; ++pss) {
            int row = mm + pss * 64;
            float4 a = *(const float4*)(Ab + (size_t)row * E_ + k0 + kq);
            As[(kq + 0) * 132 + row] = a.x;
            As[(kq + 1) * 132 + row] = a.y;
            As[(kq + 2) * 132 + row] = a.z;
            As[(kq + 3) * 132 + row] = a.w;
            float4 w = *(const float4*)(Bb + (size_t)row * E_ + k0 + kq);
            Bs[(kq + 0) * 132 + row] = w.x;
            Bs[(kq + 1) * 132 + row] = w.y;
            Bs[(kq + 2) * 132 + row] = w.z;
            Bs[(kq + 3) * 132 + row] = w.w;
        }
        __syncthreads();

#pragma unroll
        for (int k = 0; k < 16; ++k) {
            float4 t0 = *(const float4*)(As + k * 132 + ty8 * 8);
            float4 t1 = *(const float4*)(As + k * 132 + ty8 * 8 + 4);
            ulonglong2 u0 = *(const ulonglong2*)(Bs + k * 132 + tx8 * 8);
            ulonglong2 u1 = *(const ulonglong2*)(Bs + k * 132 + tx8 * 8 + 4);
            float av[8] = {t0.x, t0.y, t0.z, t0.w, t1.x, t1.y, t1.z, t1.w};
#pragma unroll
            for (int r = 0; r < 8; ++r) {
                u64t ar = splat2(av[r]);
                acc2[r][0] = fma2(ar, u0.x, acc2[r][0]);
                acc2[r][1] = fma2(ar, u0.y, acc2[r][1]);
                acc2[r][2] = fma2(ar, u1.x, acc2[r][2]);
                acc2[r][3] = fma2(ar, u1.y, acc2[r][3]);
            }
        }
    }

#pragma unroll
    for (int r = 0; r < 8; ++r) {
        int m = m0 + ty8 * 8 + r;
#pragma unroll
        for (int cg = 0; cg < 2; ++cg) {
            int n = n0 + tx8 * 8 + cg * 4;
            float4 bb = *(const float4*)(bo + n);
            float2 a0 = unpack2(acc2[r][cg * 2 + 0]);
            float2 a1 = unpack2(acc2[r][cg * 2 + 1]);
            *(float4*)(Y + (size_t)m * E_ + n) =
                make_float4(a0.x + bb.x, a0.y + bb.y, a1.x + bb.z, a1.y + bb.w);
        }
    }
}

// ---------------------------------------------------------------------------
extern "C" void kernel_launch(void* const* d_in, const int* in_sizes, int n_in,
                              void* d_out, int out_size) {
    const float* values = (const float*)d_in[0];
    const float* keys   = (const float*)d_in[1];
    const float* query  = (const float*)d_in[2];
    const int*   mask   = (const int*)d_in[3];

    // Input 4 is the scalar "size" if it was materialized; be defensive.
    int base = 4;
    if (n_in >= 10 && in_sizes[4] == 1) base = 5;
    const float* Wv = (const float*)d_in[base + 0];
    const float* Wk = (const float*)d_in[base + 1];
    const float* Wq = (const float*)d_in[base + 2];
    const float* Wo = (const float*)d_in[base + 3];
    const float* bo = (const float*)d_in[base + 4];
    float* out = (float*)d_out;

    dim3 pgrid(L_ / 64, B_ * H_, 3);
    proj_kernel<<<pgrid, 256>>>(values, keys, query, Wv, Wk, Wq);

    dim3 agrid(L_ / 64, B_ * H_);
    attn_kernel<<<agrid, 256>>>(mask);

    dim3 ogrid(E_ / 128, (B_ * L_) / 128);
    oproj_kernel<<<ogrid, 256>>>(Wo, bo, out);
}

// round 16
// speedup vs baseline: 1.0118x; 1.0007x over previous
#include <cuda_runtime.h>
#include <math.h>

// Problem constants (fixed by the reference setup_inputs).
#define B_ 8
#define L_ 1024
#define E_ 1024
#define H_ 16
#define D_ 64

typedef unsigned long long u64t;

// ---- packed fp32x2 helpers (Blackwell FFMA2 path) -------------------------
__device__ __forceinline__ u64t splat2(float x) {
    u64t r;
    unsigned u = __float_as_uint(x);
    asm("mov.b64 %0, {%1, %1};" : "=l"(r) : "r"(u));
    return r;
}
__device__ __forceinline__ u64t fma2(u64t a, u64t b, u64t c) {
    u64t d;
    asm("fma.rn.f32x2 %0, %1, %2, %3;" : "=l"(d) : "l"(a), "l"(b), "l"(c));
    return d;
}
__device__ __forceinline__ u64t mul2(u64t a, u64t b) {
    u64t d;
    asm("mul.rn.f32x2 %0, %1, %2;" : "=l"(d) : "l"(a), "l"(b));
    return d;
}
__device__ __forceinline__ float2 unpack2(u64t a) {
    unsigned lo, hi;
    asm("mov.b64 {%0, %1}, %2;" : "=r"(lo), "=r"(hi) : "l"(a));
    return make_float2(__uint_as_float(lo), __uint_as_float(hi));
}

// Scratch (allocation-free rule: __device__ globals).
// Layouts: g_Qp/g_Kp/g_Vp : [B*H][L][D]   g_Oa : [B][L][E]
__device__ float g_Qp[(size_t)B_ * H_ * L_ * D_];
__device__ float g_Kp[(size_t)B_ * H_ * L_ * D_];
__device__ float g_Vp[(size_t)B_ * H_ * L_ * D_];
__device__ float g_Oa[(size_t)B_ * L_ * E_];

// ---------------------------------------------------------------------------
// Kernel 1: per-head QKV projection, fused (blockIdx.z selects V/K/Q).
// out[b,h,l,e] = sum_d X[b,l,h*D+d] * W[h,e,d]
// Block: 64 l-rows x 64 e-cols for one (b,h). 256 threads, 4x4 micro-tile.
// ---------------------------------------------------------------------------
__global__ void __launch_bounds__(256) proj_kernel(
    const float* __restrict__ Xv, const float* __restrict__ Xk,
    const float* __restrict__ Xq, const float* __restrict__ Wv,
    const float* __restrict__ Wk, const float* __restrict__ Wq) {
    __shared__ float Xt[64 * 64];  // [d][l]
    __shared__ float Wt[64 * 64];  // [d][e]

    const int tid   = threadIdx.x;
    const int which = blockIdx.z;
    const int bh    = blockIdx.y;
    const int b     = bh >> 4;
    const int h     = bh & 15;
    const int l0    = blockIdx.x * 64;
    const int tx    = tid & 15;
    const int ty    = tid >> 4;
    const int d4    = ty * 4;

    const float* X = (which == 0) ? Xv : (which == 1) ? Xk : Xq;
    const float* W = (which == 0) ? Wv : (which == 1) ? Wk : Wq;
    const float* Xb = X + ((size_t)b * L_ + l0) * E_ + h * D_;
    const float* Wh = W + (size_t)h * D_ * D_;

#pragma unroll
    for (int r = 0; r < 4; ++r) {
        int row = tx + r * 16;
        float4 x = *(const float4*)(Xb + (size_t)row * E_ + d4);
        Xt[(d4 + 0) * 64 + row] = x.x;
        Xt[(d4 + 1) * 64 + row] = x.y;
        Xt[(d4 + 2) * 64 + row] = x.z;
        Xt[(d4 + 3) * 64 + row] = x.w;
        float4 w = *(const float4*)(Wh + (size_t)row * D_ + d4);
        Wt[(d4 + 0) * 64 + row] = w.x;
        Wt[(d4 + 1) * 64 + row] = w.y;
        Wt[(d4 + 2) * 64 + row] = w.z;
        Wt[(d4 + 3) * 64 + row] = w.w;
    }
    __syncthreads();

    u64t acc2[4][2];
#pragma unroll
    for (int r = 0; r < 4; ++r) { acc2[r][0] = 0ull; acc2[r][1] = 0ull; }

#pragma unroll 8
    for (int d = 0; d < 64; ++d) {
        float4 xf = *(const float4*)(Xt + d * 64 + ty * 4);          // broadcast
        ulonglong2 wf = *(const ulonglong2*)(Wt + d * 64 + tx * 4);  // packed pairs
        u64t x0 = splat2(xf.x), x1 = splat2(xf.y), x2 = splat2(xf.z), x3 = splat2(xf.w);
        acc2[0][0] = fma2(x0, wf.x, acc2[0][0]);
        acc2[0][1] = fma2(x0, wf.y, acc2[0][1]);
        acc2[1][0] = fma2(x1, wf.x, acc2[1][0]);
        acc2[1][1] = fma2(x1, wf.y, acc2[1][1]);
        acc2[2][0] = fma2(x2, wf.x, acc2[2][0]);
        acc2[2][1] = fma2(x2, wf.y, acc2[2][1]);
        acc2[3][0] = fma2(x3, wf.x, acc2[3][0]);
        acc2[3][1] = fma2(x3, wf.y, acc2[3][1]);
    }

    float* O = (which == 0) ? g_Vp : (which == 1) ? g_Kp : g_Qp;
    O += ((size_t)bh * L_ + l0) * D_;
#pragma unroll
    for (int r = 0; r < 4; ++r) {
        float2 a = unpack2(acc2[r][0]);
        float2 c = unpack2(acc2[r][1]);
        *(float4*)(O + (size_t)(ty * 4 + r) * D_ + tx * 4) =
            make_float4(a.x, a.y, c.x, c.y);
    }
}

// ---------------------------------------------------------------------------
// Kernel 2: flash-style attention for one (b,h) and 64 query rows.
// S = (Q K^T) masked, scaled by 1/8; online softmax; O = P V.
// 256 threads, 48 KB smem. f32x2-packed FMAs in both GEMMs.
// ---------------------------------------------------------------------------
__global__ void __launch_bounds__(256) attn_kernel(const int* __restrict__ mask) {
    __shared__ float Qt[64 * 64];   // [d][i]
    __shared__ float KPt[64 * 64];  // K phase: [d][j];  P phase: [i][j]
    __shared__ float Vs[64 * 64];   // [j][d]

    const int tid = threadIdx.x;
    const int bh  = blockIdx.y;
    const int b   = bh >> 4;
    const int i0  = blockIdx.x * 64;
    const int tx  = tid & 15;
    const int ty  = tid >> 4;
    const int d4  = ty * 4;

    const float* Qb = g_Qp + (size_t)bh * L_ * D_;
    const float* Kb = g_Kp + (size_t)bh * L_ * D_;
    const float* Vb = g_Vp + (size_t)bh * L_ * D_;
    const int*   mb = mask + (size_t)b * L_ * L_;

    // Load Q tile transposed once.
#pragma unroll
    for (int r = 0; r < 4; ++r) {
        int row = tx + r * 16;
        float4 q = *(const float4*)(Qb + (size_t)(i0 + row) * D_ + d4);
        Qt[(d4 + 0) * 64 + row] = q.x;
        Qt[(d4 + 1) * 64 + row] = q.y;
        Qt[(d4 + 2) * 64 + row] = q.z;
        Qt[(d4 + 3) * 64 + row] = q.w;
    }

    float m_i[4], l_i[4];
    u64t acc2[4][2];
#pragma unroll
    for (int r = 0; r < 4; ++r) {
        m_i[r] = -1.0e30f;
        l_i[r] = 0.0f;
        acc2[r][0] = 0ull;
        acc2[r][1] = 0ull;
    }

    for (int j0 = 0; j0 < L_; j0 += 64) {
        __syncthreads();  // previous P/V consumers done (covers Qt on iter 0)
#pragma unroll
        for (int r = 0; r < 4; ++r) {
            int row = tx + r * 16;
            float4 k = *(const float4*)(Kb + (size_t)(j0 + row) * D_ + d4);
            KPt[(d4 + 0) * 64 + row] = k.x;
            KPt[(d4 + 1) * 64 + row] = k.y;
            KPt[(d4 + 2) * 64 + row] = k.z;
            KPt[(d4 + 3) * 64 + row] = k.w;
            int rowv = ty + r * 16;
            float4 v = *(const float4*)(Vb + (size_t)(j0 + rowv) * D_ + tx * 4);
            *(float4*)(Vs + rowv * 64 + tx * 4) = v;
        }
        __syncthreads();

        // S = Q K^T (packed pairs along j)
        u64t s2[4][2];
#pragma unroll
        for (int r = 0; r < 4; ++r) { s2[r][0] = 0ull; s2[r][1] = 0ull; }

#pragma unroll 8
        for (int d = 0; d < 64; ++d) {
            float4 qf = *(const float4*)(Qt + d * 64 + ty * 4);           // broadcast
            ulonglong2 kf = *(const ulonglong2*)(KPt + d * 64 + tx * 4);  // packed
            u64t q0 = splat2(qf.x), q1 = splat2(qf.y), q2 = splat2(qf.z), q3 = splat2(qf.w);
            s2[0][0] = fma2(q0, kf.x, s2[0][0]);
            s2[0][1] = fma2(q0, kf.y, s2[0][1]);
            s2[1][0] = fma2(q1, kf.x, s2[1][0]);
            s2[1][1] = fma2(q1, kf.y, s2[1][1]);
            s2[2][0] = fma2(q2, kf.x, s2[2][0]);
            s2[2][1] = fma2(q2, kf.y, s2[2][1]);
            s2[3][0] = fma2(q3, kf.x, s2[3][0]);
            s2[3][1] = fma2(q3, kf.y, s2[3][1]);
        }

        // Mask (-1e20 pre-scale, exactly like reference), scale, online softmax.
        float p[4][4];
#pragma unroll
        for (int r = 0; r < 4; ++r) {
            float s[4];
            float2 a0 = unpack2(s2[r][0]);
            float2 a1 = unpack2(s2[r][1]);
            s[0] = a0.x; s[1] = a0.y; s[2] = a1.x; s[3] = a1.y;

            int4 mk = *(const int4*)(mb + (size_t)(i0 + ty * 4 + r) * L_ + j0 + tx * 4);
            s[0] = 0.125f * ((mk.x == 0) ? -1.0e20f : s[0]);
            s[1] = 0.125f * ((mk.y == 0) ? -1.0e20f : s[1]);
            s[2] = 0.125f * ((mk.z == 0) ? -1.0e20f : s[2]);
            s[3] = 0.125f * ((mk.w == 0) ? -1.0e20f : s[3]);

            float mloc = fmaxf(fmaxf(s[0], s[1]), fmaxf(s[2], s[3]));
#pragma unroll
            for (int o = 8; o > 0; o >>= 1)
                mloc = fmaxf(mloc, __shfl_xor_sync(0xffffffffu, mloc, o));
            float mnew = fmaxf(m_i[r], mloc);
            float a = __expf(m_i[r] - mnew);
            float rsum = 0.0f;
#pragma unroll
            for (int c = 0; c < 4; ++c) {
                p[r][c] = __expf(s[c] - mnew);
                rsum += p[r][c];
            }
#pragma unroll
            for (int o = 8; o > 0; o >>= 1)
                rsum += __shfl_xor_sync(0xffffffffu, rsum, o);
            l_i[r] = l_i[r] * a + rsum;
            m_i[r] = mnew;
            u64t a2 = splat2(a);
            acc2[r][0] = mul2(acc2[r][0], a2);
            acc2[r][1] = mul2(acc2[r][1], a2);
        }

        __syncthreads();  // everyone done reading K from KPt
#pragma unroll
        for (int r = 0; r < 4; ++r) {
            *(float4*)(KPt + (ty * 4 + r) * 64 + tx * 4) =
                make_float4(p[r][0], p[r][1], p[r][2], p[r][3]);
        }
        __syncthreads();

        // O[i][d] += sum_j P[i][j] * V[j][d]   (packed pairs along d)
#pragma unroll 8
        for (int j = 0; j < 64; ++j) {
            ulonglong2 vf = *(const ulonglong2*)(Vs + j * 64 + tx * 4);
            u64t p0 = splat2(KPt[(ty * 4 + 0) * 64 + j]);  // broadcast reads
            u64t p1 = splat2(KPt[(ty * 4 + 1) * 64 + j]);
            u64t p2 = splat2(KPt[(ty * 4 + 2) * 64 + j]);
            u64t p3 = splat2(KPt[(ty * 4 + 3) * 64 + j]);
            acc2[0][0] = fma2(p0, vf.x, acc2[0][0]);
            acc2[0][1] = fma2(p0, vf.y, acc2[0][1]);
            acc2[1][0] = fma2(p1, vf.x, acc2[1][0]);
            acc2[1][1] = fma2(p1, vf.y, acc2[1][1]);
            acc2[2][0] = fma2(p2, vf.x, acc2[2][0]);
            acc2[2][1] = fma2(p2, vf.y, acc2[2][1]);
            acc2[3][0] = fma2(p3, vf.x, acc2[3][0]);
            acc2[3][1] = fma2(p3, vf.y, acc2[3][1]);
        }
    }

    // Epilogue: normalize, write concat-head layout [B][L][E].
    const int h = bh & 15;
    float* Ob = g_Oa + ((size_t)b * L_ + i0) * E_ + h * D_;
#pragma unroll
    for (int r = 0; r < 4; ++r) {
        float inv = 1.0f / l_i[r];
        float2 a = unpack2(acc2[r][0]);
        float2 c = unpack2(acc2[r][1]);
        *(float4*)(Ob + (size_t)(ty * 4 + r) * E_ + tx * 4) =
            make_float4(a.x * inv, a.y * inv, c.x * inv, c.y * inv);
    }
}

// ---------------------------------------------------------------------------
// Kernel 3: output projection  Y = Oa @ Wo^T + bo.
// [8192 x 1024] x [1024 x 1024]^T. 128x128 tiles, BK=16, 8x8 micro-tile, f32x2.
// ---------------------------------------------------------------------------
__global__ void __launch_bounds__(256) oproj_kernel(const float* __restrict__ Wo,
                                                    const float* __restrict__ bo,
                                                    float* __restrict__ Y) {
    __shared__ float As[16 * 132];  // [k][m], padded (132*4 = 528 B, 16B-multiple)
    __shared__ float Bs[16 * 132];  // [k][n], padded

    const int tid = threadIdx.x;
    const int n0  = blockIdx.x * 128;
    const int m0  = blockIdx.y * 128;
    const int tx8 = tid & 15;
    const int ty8 = tid >> 4;
    const int kq  = (tid >> 6) * 4;  // 0,4,8,12
    const int mm  = tid & 63;

    u64t acc2[8][4];
#pragma unroll
    for (int r = 0; r < 8; ++r)
#pragma unroll
        for (int c = 0; c < 4; ++c) acc2[r][c] = 0ull;

    const float* Ab = g_Oa + (size_t)m0 * E_;
    const float* Bb = Wo + (size_t)n0 * E_;

    for (int k0 = 0; k0 < E_; k0 += 16) {
        __syncthreads();
#pragma unroll
        for (int pss = 0; pss < 2; ++pss) {
            int row = mm + pss * 64;
            float4 a = *(const float4*)(Ab + (size_t)row * E_ + k0 + kq);
            As[(kq + 0) * 132 + row] = a.x;
            As[(kq + 1) * 132 + row] = a.y;
            As[(kq + 2) * 132 + row] = a.z;
            As[(kq + 3) * 132 + row] = a.w;
            float4 w = *(const float4*)(Bb + (size_t)row * E_ + k0 + kq);
            Bs[(kq + 0) * 132 + row] = w.x;
            Bs[(kq + 1) * 132 + row] = w.y;
            Bs[(kq + 2) * 132 + row] = w.z;
            Bs[(kq + 3) * 132 + row] = w.w;
        }
        __syncthreads();

#pragma unroll
        for (int k = 0; k < 16; ++k) {
            float4 t0 = *(const float4*)(As + k * 132 + ty8 * 8);
            float4 t1 = *(const float4*)(As + k * 132 + ty8 * 8 + 4);
            ulonglong2 u0 = *(const ulonglong2*)(Bs + k * 132 + tx8 * 8);
            ulonglong2 u1 = *(const ulonglong2*)(Bs + k * 132 + tx8 * 8 + 4);
            float av[8] = {t0.x, t0.y, t0.z, t0.w, t1.x, t1.y, t1.z, t1.w};
#pragma unroll
            for (int r = 0; r < 8; ++r) {
                u64t ar = splat2(av[r]);
                acc2[r][0] = fma2(ar, u0.x, acc2[r][0]);
                acc2[r][1] = fma2(ar, u0.y, acc2[r][1]);
                acc2[r][2] = fma2(ar, u1.x, acc2[r][2]);
                acc2[r][3] = fma2(ar, u1.y, acc2[r][3]);
            }
        }
    }

#pragma unroll
    for (int r = 0; r < 8; ++r) {
        int m = m0 + ty8 * 8 + r;
#pragma unroll
        for (int cg = 0; cg < 2; ++cg) {
            int n = n0 + tx8 * 8 + cg * 4;
            float4 bb = *(const float4*)(bo + n);
            float2 a0 = unpack2(acc2[r][cg * 2 + 0]);
            float2 a1 = unpack2(acc2[r][cg * 2 + 1]);
            *(float4*)(Y + (size_t)m * E_ + n) =
                make_float4(a0.x + bb.x, a0.y + bb.y, a1.x + bb.z, a1.y + bb.w);
        }
    }
}

// ---------------------------------------------------------------------------
extern "C" void kernel_launch(void* const* d_in, const int* in_sizes, int n_in,
                              void* d_out, int out_size) {
    const float* values = (const float*)d_in[0];
    const float* keys   = (const float*)d_in[1];
    const float* query  = (const float*)d_in[2];
    const int*   mask   = (const int*)d_in[3];

    // Input 4 is the scalar "size" if it was materialized; be defensive.
    int base = 4;
    if (n_in >= 10 && in_sizes[4] == 1) base = 5;
    const float* Wv = (const float*)d_in[base + 0];
    const float* Wk = (const float*)d_in[base + 1];
    const float* Wq = (const float*)d_in[base + 2];
    const float* Wo = (const float*)d_in[base + 3];
    const float* bo = (const float*)d_in[base + 4];
    float* out = (float*)d_out;

    dim3 pgrid(L_ / 64, B_ * H_, 3);
    proj_kernel<<<pgrid, 256>>>(values, keys, query, Wv, Wk, Wq);

    dim3 agrid(L_ / 64, B_ * H_);
    attn_kernel<<<agrid, 256>>>(mask);

    dim3 ogrid(E_ / 128, (B_ * L_) / 128);
    oproj_kernel<<<ogrid, 256>>>(Wo, bo, out);
}